// round 5
// baseline (speedup 1.0000x reference)
#include <cuda_runtime.h>
#include <math.h>
#include <stdint.h>

#define BATCH 16
#define T_LEN 131072
#define HOP 256
#define NFFT 2048
#define NBINS 1025
#define NFR 513
#define NFRT (BATCH*NFR)          /* 8208 */
#define NPT 257                    /* frame pairs per batch (last has no B) */
#define NPAIR (BATCH*NPT)          /* 4112 */
#define NMELS 80
#define MIN_P 32
#define NLAG 224
#define L_OLA 133120               /* NFFT + HOP*(NFR-1) */
#define NTOT (BATCH*NBINS*NFR)     /* 8413200 */
#define MOM (0.99f/1.99f)

#define PAD(i) ((i) + ((i)>>3))
#define ZLEN 2304                  /* PAD(2047)=2302 */

// ---------------- scratch (static device globals; no allocs) ----------------
__device__ float  g_win[NFFT];
__device__ float  g_env[L_OLA];
__device__ int    g_fbi[NBINS];
__device__ float2 g_fbw[NBINS];
__device__ float  g_lin[NFRT*NBINS];
__device__ float2 g_ang[NFRT*NBINS];
__device__ float2 g_tprev[NFRT*NBINS];
__device__ float  g_frames[NFRT*NFFT];
__device__ float  g_inv[BATCH*T_LEN];

// ---------------- threefry-2x32-20 (matches jax partitionable) ----------------
__host__ __device__ __forceinline__ unsigned rotl32(unsigned x, int r){ return (x<<r)|(x>>(32-r)); }
__host__ __device__ inline void tf2x32(unsigned k0,unsigned k1,unsigned x0,unsigned x1,unsigned&o0,unsigned&o1){
  unsigned k2 = k0^k1^0x1BD11BDAu;
  x0+=k0; x1+=k1;
  #define TFR(r) { x0+=x1; x1=rotl32(x1,(r)); x1^=x0; }
  TFR(13) TFR(15) TFR(26) TFR(6)  x0+=k1; x1+=k2+1u;
  TFR(17) TFR(29) TFR(16) TFR(24) x0+=k2; x1+=k0+2u;
  TFR(13) TFR(15) TFR(26) TFR(6)  x0+=k0; x1+=k1+3u;
  TFR(17) TFR(29) TFR(16) TFR(24) x0+=k1; x1+=k2+4u;
  TFR(13) TFR(15) TFR(26) TFR(6)  x0+=k2; x1+=k0+5u;
  #undef TFR
  o0=x0; o1=x1;
}
__device__ __forceinline__ float u01(unsigned bits){
  return __uint_as_float((bits>>9) | 0x3f800000u) - 1.0f;
}
__device__ __forceinline__ int refl(int j, int n){
  if (j < 0) j = -j;
  if (j >= n) j = 2*n - 2 - j;
  return j;
}

// ---------------- register radix-8 DFT (DIF), DIR=+1 fwd / -1 inv ----------------
template<int DIR>
__device__ __forceinline__ void dft8(float* ar, float* ai){
  const float r2 = 0.70710678118654752f;
  const float d = (float)DIR;
  float t0r=ar[0]+ar[4], t0i=ai[0]+ai[4];
  float t4r=ar[0]-ar[4], t4i=ai[0]-ai[4];
  float t1r=ar[1]+ar[5], t1i=ai[1]+ai[5];
  float t5r=ar[1]-ar[5], t5i=ai[1]-ai[5];
  float t2r=ar[2]+ar[6], t2i=ai[2]+ai[6];
  float t6r=ar[2]-ar[6], t6i=ai[2]-ai[6];
  float t3r=ar[3]+ar[7], t3i=ai[3]+ai[7];
  float t7r=ar[3]-ar[7], t7i=ai[3]-ai[7];
  { float a=t5r,b=t5i; t5r=r2*(a+d*b); t5i=r2*(b-d*a); }      // *w8^1
  { float a=t6r,b=t6i; t6r=d*b; t6i=-d*a; }                   // *w8^2 = -i*d
  { float a=t7r,b=t7i; t7r=r2*(d*b-a); t7i=-r2*(b+d*a); }     // *w8^3
  float u0r=t0r+t2r,u0i=t0i+t2i, u1r=t0r-t2r,u1i=t0i-t2i;
  float u2r=t1r+t3r,u2i=t1i+t3i, u3r=t1r-t3r,u3i=t1i-t3i;
  float vr=d*u3i, vi=-d*u3r;
  ar[0]=u0r+u2r; ai[0]=u0i+u2i;
  ar[4]=u0r-u2r; ai[4]=u0i-u2i;
  ar[2]=u1r+vr;  ai[2]=u1i+vi;
  ar[6]=u1r-vr;  ai[6]=u1i-vi;
  u0r=t4r+t6r; u0i=t4i+t6i; u1r=t4r-t6r; u1i=t4i-t6i;
  u2r=t5r+t7r; u2i=t5i+t7i; u3r=t5r-t7r; u3i=t5i-t7i;
  vr=d*u3i; vi=-d*u3r;
  ar[1]=u0r+u2r; ai[1]=u0i+u2i;
  ar[5]=u0r-u2r; ai[5]=u0i-u2i;
  ar[3]=u1r+vr;  ai[3]=u1i+vi;
  ar[7]=u1r-vr;  ai[7]=u1i-vi;
}

// ---------------- size-2048 Stockham FFT, radix 8*8*8*4, single SoA buffer ----------------
template<int DIR>
__device__ __forceinline__ void fft2048_r8(float* Zr, float* Zi, int tid){
  #pragma unroll
  for (int st = 0; st < 3; ++st){
    const int s = (st==0) ? 1 : (st==1) ? 8 : 64;
    int q = tid & (s-1);
    int ps = tid - q;
    float ar[8], ai[8];
    #pragma unroll
    for (int j=0;j<8;++j){ int idx = tid + (j<<8); ar[j]=Zr[PAD(idx)]; ai[j]=Zi[PAD(idx)]; }
    __syncthreads();
    dft8<DIR>(ar, ai);
    float sn, cs;
    sincospif((float)ps * (1.0f/1024.0f), &sn, &cs);
    float w1r = cs, w1i = -(float)DIR * sn;
    float wr = w1r, wi = w1i;
    int base = q + (ps<<3);
    Zr[PAD(base)] = ar[0]; Zi[PAD(base)] = ai[0];
    #pragma unroll
    for (int k=1;k<8;++k){
      float br = ar[k]*wr - ai[k]*wi;
      float bi = ar[k]*wi + ai[k]*wr;
      int idx = base + s*k;
      Zr[PAD(idx)] = br; Zi[PAD(idx)] = bi;
      float nwr = wr*w1r - wi*w1i; wi = wr*w1i + wi*w1r; wr = nwr;
    }
    __syncthreads();
  }
  float cr[8], ci[8];
  #pragma unroll
  for (int h=0; h<2; ++h){
    int i = tid + (h<<8);
    #pragma unroll
    for (int j=0;j<4;++j){ int idx = i + (j<<9); cr[h*4+j]=Zr[PAD(idx)]; ci[h*4+j]=Zi[PAD(idx)]; }
  }
  __syncthreads();
  const float d = (float)DIR;
  #pragma unroll
  for (int h=0;h<2;++h){
    int i = tid + (h<<8);
    float u0r=cr[h*4]+cr[h*4+2], u0i=ci[h*4]+ci[h*4+2];
    float u1r=cr[h*4]-cr[h*4+2], u1i=ci[h*4]-ci[h*4+2];
    float u2r=cr[h*4+1]+cr[h*4+3], u2i=ci[h*4+1]+ci[h*4+3];
    float u3r=cr[h*4+1]-cr[h*4+3], u3i=ci[h*4+1]-ci[h*4+3];
    float vr=d*u3i, vi=-d*u3r;
    Zr[PAD(i)]      = u0r+u2r; Zi[PAD(i)]      = u0i+u2i;
    Zr[PAD(i+512)]  = u1r+vr;  Zi[PAD(i+512)]  = u1i+vi;
    Zr[PAD(i+1024)] = u0r-u2r; Zi[PAD(i+1024)] = u0i-u2i;
    Zr[PAD(i+1536)] = u1r-vr;  Zi[PAD(i+1536)] = u1i-vi;
  }
  __syncthreads();
}

// ---------------- init tables ----------------
__global__ void k_tables(){
  int idx = blockIdx.x*blockDim.x + threadIdx.x;
  if (idx < 2048){
    g_win[idx] = (float)(0.5 - 0.5*cos(2.0*M_PI*(double)idx/2048.0));
  } else if (idx < 2048+L_OLA){
    int i = idx - 2048;
    int flo = (i - 1792) >> 8; if (flo < 0) flo = 0;
    int fhi = i >> 8;          if (fhi > NFR-1) fhi = NFR-1;
    double acc = 0.0;
    for (int f = flo; f <= fhi; ++f){
      int n = i - 256*f;
      double w = 0.5 - 0.5*cos(2.0*M_PI*(double)n/2048.0);
      acc += w*w;
    }
    g_env[i] = (float)acc;
  } else {
    int f = idx - 2048 - L_OLA;
    if (f < NBINS){
      double mmax = 2595.0*log10(1.0 + 8000.0/700.0);
      double freq = (double)f * 8000.0/1024.0;
      int first = -1; float w0 = 0.f, w1 = 0.f;
      for (int m = 0; m < NMELS; ++m){
        double fp0 = 700.0*(pow(10.0, (double)(m  )*mmax/81.0/2595.0) - 1.0);
        double fp1 = 700.0*(pow(10.0, (double)(m+1)*mmax/81.0/2595.0) - 1.0);
        double fp2 = 700.0*(pow(10.0, (double)(m+2)*mmax/81.0/2595.0) - 1.0);
        double dn = (freq - fp0)/(fp1 - fp0);
        double up = (fp2 - freq)/(fp2 - fp1);
        double v = dn < up ? dn : up;
        if (v > 0.0){
          if (first < 0){ first = m; w0 = (float)v; }
          else w1 = (float)v;
        }
      }
      g_fbi[f] = first;
      g_fbw[f] = make_float2(w0, w1);
    }
  }
}

// ---------------- initial random phases (coalesced writes; counter computed) ----------------
__global__ void k_angles(unsigned kr0,unsigned kr1,unsigned ki0,unsigned ki1){
  int m = blockIdx.x*blockDim.x + threadIdx.x;   // m indexes (b,t,f) storage layout
  if (m >= NTOT) return;
  int f  = m % NBINS;
  int bt = m / NBINS;
  int t  = bt % NFR;
  int b  = bt / NFR;
  unsigned e = ((unsigned)(b*NBINS + f))*((unsigned)NFR) + (unsigned)t; // jax (B,F,T) linear idx
  unsigned r0,r1,i0,i1;
  tf2x32(kr0,kr1, 0u, e, r0,r1);
  tf2x32(ki0,ki1, 0u, e, i0,i1);
  g_ang[m]   = make_float2(u01(r0^r1), u01(i0^i1));
  g_tprev[m] = make_float2(0.f, 0.f);
}

// ---------------- f0 / loudness + MLP (8 frames per block) ----------------
__global__ void k_feats_mlp(const float* __restrict__ x,
                            const float* __restrict__ W1, const float* __restrict__ b1,
                            const float* __restrict__ W2, const float* __restrict__ b2,
                            const float* __restrict__ W3, const float* __restrict__ b3,
                            float* __restrict__ outc){
  __shared__ float s[512];
  __shared__ float h1s[8*256];
  __shared__ float h2s[8*256];
  __shared__ float rv[256];
  __shared__ int   ri[256];
  __shared__ float feat[8][2];
  int tid = threadIdx.x;
  int base = blockIdx.x * 8;

  for (int u = 0; u < 8; ++u){
    int fr = base + u;
    int b = fr / NFR, t = fr % NFR;
    const float* xb = x + (size_t)b * T_LEN;
    for (int k = tid; k < 512; k += 256)
      s[k] = xb[refl(t*HOP + k - 256, T_LEN)];
    __syncthreads();
    float ss = s[tid]*s[tid] + s[tid+256]*s[tid+256];
    rv[tid] = ss; __syncthreads();
    for (int off = 128; off; off >>= 1){
      if (tid < off) rv[tid] += rv[tid+off];
      __syncthreads();
    }
    float sumsq = rv[0];
    __syncthreads();
    float v = -1e30f; int idx = 0;
    if (tid < NLAG){
      int lag = tid + MIN_P;
      float acc = 0.f;
      for (int t2 = 0; t2 < 512 - lag; ++t2) acc += s[t2]*s[t2+lag];
      v = acc; idx = tid;
    }
    rv[tid] = v; ri[tid] = idx; __syncthreads();
    for (int off = 128; off; off >>= 1){
      if (tid < off){
        float vo = rv[tid+off]; int io = ri[tid+off];
        if (vo > rv[tid] || (vo == rv[tid] && io < ri[tid])){ rv[tid]=vo; ri[tid]=io; }
      }
      __syncthreads();
    }
    if (tid == 0){
      float period = (float)(ri[0] + MIN_P);
      float f0 = 16000.0f/(period + 1e-8f);
      f0 = fminf(fmaxf(f0, 50.0f), 500.0f);
      float loud = 20.0f*log10f(sqrtf(sumsq/512.0f) + 1e-8f);
      feat[u][0] = f0; feat[u][1] = loud;
    }
    __syncthreads();
    float f0 = feat[u][0], ld = feat[u][1];
    float z = f0*W1[tid] + ld*W1[256+tid] + b1[tid];
    h1s[u*256+tid] = z > 0.f ? z : expm1f(z);
    __syncthreads();
  }
  float acc[8];
  #pragma unroll
  for (int u = 0; u < 8; ++u) acc[u] = b2[tid];
  for (int k = 0; k < 256; ++k){
    float w = W2[k*256 + tid];
    #pragma unroll
    for (int u = 0; u < 8; ++u) acc[u] += h1s[u*256+k]*w;
  }
  #pragma unroll
  for (int u = 0; u < 8; ++u){
    float z = acc[u];
    h2s[u*256+tid] = z > 0.f ? z : expm1f(z);
  }
  __syncthreads();
  int o = tid & 63;
  for (int pass = 0; pass < 2; ++pass){
    int u = (tid >> 6) + pass*4;
    float a3 = b3[o];
    for (int k = 0; k < 256; ++k) a3 += h2s[u*256+k]*W3[k*64 + o];
    int fr = base + u;
    outc[(size_t)fr*64 + o] = a3;
  }
}

// ---------------- STFT (2 frames packed) -> mag -> mel (sparse scatter) -> linear ----------------
__global__ void k_stft_lin(const float* __restrict__ x){
  __shared__ float Zr[ZLEN], Zi[ZLEN];
  __shared__ float mel[2][NMELS];
  int tid = threadIdx.x;
  int pb = blockIdx.x;
  int b = pb / NPT, pt = pb % NPT;
  int t0 = 2*pt;
  bool hasB = (t0 + 1 < NFR);
  int fr0 = b*NFR + t0;
  const float* xb = x + (size_t)b * T_LEN;
  for (int k = tid; k < 2048; k += 256){
    float w = g_win[k];
    Zr[PAD(k)] = xb[refl(t0*HOP + k - 1024, T_LEN)] * w;
    float vb = 0.f;
    if (hasB) vb = xb[refl((t0+1)*HOP + k - 1024, T_LEN)] * w;
    Zi[PAD(k)] = vb;
  }
  if (tid < 2*NMELS) ((float*)mel)[tid] = 0.f;
  __syncthreads();
  fft2048_r8<1>(Zr, Zi, tid);
  for (int k = tid; k <= 1024; k += 256){
    int m = (2048 - k) & 2047;
    float zkr=Zr[PAD(k)], zki=Zi[PAD(k)], zmr=Zr[PAD(m)], zmi=Zi[PAD(m)];
    float far_ = 0.5f*(zkr + zmr), fai = 0.5f*(zki - zmi);
    float dr = zkr - zmr, di = zki + zmi;
    float fbr = 0.5f*di, fbi = -0.5f*dr;
    float maga = sqrtf(far_*far_ + fai*fai);
    float magb = sqrtf(fbr*fbr + fbi*fbi);
    int i = g_fbi[k];
    float2 w = g_fbw[k];
    if (i >= 0){
      atomicAdd(&mel[0][i], maga*w.x);
      atomicAdd(&mel[1][i], magb*w.x);
      if (w.y != 0.f && i+1 < NMELS){
        atomicAdd(&mel[0][i+1], maga*w.y);
        atomicAdd(&mel[1][i+1], magb*w.y);
      }
    }
  }
  __syncthreads();
  for (int f = tid; f <= 1024; f += 256){
    float src = fmaxf((f + 0.5f)*(80.0f/1025.0f) - 0.5f, 0.0f);
    int i0 = (int)floorf(src); if (i0 > 79) i0 = 79; if (i0 < 0) i0 = 0;
    int i1 = i0 + 1; if (i1 > 79) i1 = 79;
    float w = src - (float)i0;
    g_lin[(size_t)fr0*NBINS + f] = (1.0f - w)*mel[0][i0] + w*mel[0][i1];
    if (hasB) g_lin[(size_t)(fr0+1)*NBINS + f] = (1.0f - w)*mel[1][i0] + w*mel[1][i1];
  }
}

// ---------------- inverse FFT of spec*angles (2 frames packed) -> windowed frames ----------------
__global__ void k_ifft_frames(){
  __shared__ float Zr[ZLEN], Zi[ZLEN];
  int tid = threadIdx.x;
  int pb = blockIdx.x;
  int b = pb / NPT, pt = pb % NPT;
  int t0 = 2*pt;
  bool hasB = (t0 + 1 < NFR);
  int fr0 = b*NFR + t0;
  const float*  lin0 = g_lin + (size_t)fr0*NBINS;
  const float2* ang0 = g_ang + (size_t)fr0*NBINS;
  for (int k = tid; k <= 1024; k += 256){
    // irfft ignores Im at DC/Nyquist -> zero so each half-spectrum is Hermitian
    float msk = (k == 0 || k == 1024) ? 0.f : 1.f;
    float  L = lin0[k];
    float2 a = ang0[k];
    float ar_ = L*a.x, ai_ = L*a.y*msk;
    float br_ = 0.f, bi_ = 0.f;
    if (hasB){
      float Lb = lin0[NBINS + k];
      float2 ab = ang0[NBINS + k];
      br_ = Lb*ab.x; bi_ = Lb*ab.y*msk;
    }
    Zr[PAD(k)] = ar_ - bi_;
    Zi[PAD(k)] = ai_ + br_;
    if (k > 0 && k < 1024){
      int mm = 2048 - k;
      Zr[PAD(mm)] = ar_ + bi_;
      Zi[PAD(mm)] = br_ - ai_;
    }
  }
  __syncthreads();
  fft2048_r8<-1>(Zr, Zi, tid);
  float* oa = g_frames + (size_t)fr0 * 2048;
  for (int n = tid; n < 2048; n += 256){
    float w = g_win[n] * (1.0f/2048.0f);
    oa[n] = Zr[PAD(n)] * w;
    if (hasB) oa[2048 + n] = Zi[PAD(n)] * w;
  }
}

// ---------------- overlap-add gather (deterministic) ----------------
__global__ void k_ola(float* __restrict__ out_final, int is_final){
  int gid = blockIdx.x*blockDim.x + threadIdx.x;
  if (gid >= BATCH*T_LEN) return;
  int b = gid >> 17;
  int i = gid & (T_LEN - 1);
  int pos = i + 1024;
  int flo = (pos - 1792) >> 8; if (flo < 0) flo = 0;
  int fhi = pos >> 8;          if (fhi > NFR-1) fhi = NFR-1;
  const float* fbuf = g_frames + (size_t)b * NFR * 2048;
  float acc = 0.f;
  for (int f = flo; f <= fhi; ++f)
    acc += fbuf[(size_t)f*2048 + (pos - (f<<8))];
  float e = g_env[pos];
  float r = acc / (e > 1e-11f ? e : 1.0f);
  if (is_final) out_final[gid] = r;
  else          g_inv[gid] = r;
}

// ---------------- STFT of inv (2 frames packed) + phase update ----------------
__global__ void k_stft_update(){
  __shared__ float Zr[ZLEN], Zi[ZLEN];
  int tid = threadIdx.x;
  int pb = blockIdx.x;
  int b = pb / NPT, pt = pb % NPT;
  int t0 = 2*pt;
  bool hasB = (t0 + 1 < NFR);
  int fr0 = b*NFR + t0;
  const float* xb = g_inv + (size_t)b * T_LEN;
  for (int k = tid; k < 2048; k += 256){
    float w = g_win[k];
    Zr[PAD(k)] = xb[refl(t0*HOP + k - 1024, T_LEN)] * w;
    float vb = 0.f;
    if (hasB) vb = xb[refl((t0+1)*HOP + k - 1024, T_LEN)] * w;
    Zi[PAD(k)] = vb;
  }
  __syncthreads();
  fft2048_r8<1>(Zr, Zi, tid);
  float2* angp = g_ang   + (size_t)fr0*NBINS;
  float2* tpp  = g_tprev + (size_t)fr0*NBINS;
  for (int k = tid; k <= 1024; k += 256){
    int m = (2048 - k) & 2047;
    float zkr=Zr[PAD(k)], zki=Zi[PAD(k)], zmr=Zr[PAD(m)], zmi=Zi[PAD(m)];
    float rar = 0.5f*(zkr + zmr), rai = 0.5f*(zki - zmi);
    float dr = zkr - zmr, di = zki + zmi;
    float rbr = 0.5f*di, rbi = -0.5f*dr;
    float2 tp = tpp[k];
    float ax = rar - MOM*tp.x, ay = rai - MOM*tp.y;
    float mg = sqrtf(ax*ax + ay*ay) + 1e-16f;
    angp[k] = make_float2(ax/mg, ay/mg);
    tpp[k]  = make_float2(rar, rai);
    if (hasB){
      float2 tpb = tpp[NBINS + k];
      float bx = rbr - MOM*tpb.x, by = rbi - MOM*tpb.y;
      float mb = sqrtf(bx*bx + by*by) + 1e-16f;
      angp[NBINS + k] = make_float2(bx/mb, by/mb);
      tpp[NBINS + k]  = make_float2(rbr, rbi);
    }
  }
}

// ---------------- launch ----------------
extern "C" void kernel_launch(void* const* d_in, const int* in_sizes, int n_in,
                              void* d_out, int out_size){
  const float* x  = (const float*)d_in[0];
  const float* W1 = (const float*)d_in[1];
  const float* b1 = (const float*)d_in[2];
  const float* W2 = (const float*)d_in[3];
  const float* b2 = (const float*)d_in[4];
  const float* W3 = (const float*)d_in[5];
  const float* b3 = (const float*)d_in[6];
  float* out  = (float*)d_out;
  float* outc = out + (size_t)BATCH*T_LEN;

  // jax.random.key(42)=(0,42); partitionable split:
  // kr = threefry((0,42),(0,0)), ki = threefry((0,42),(0,1))
  unsigned kr0,kr1,ki0,ki1;
  tf2x32(0u, 42u, 0u, 0u, kr0, kr1);
  tf2x32(0u, 42u, 0u, 1u, ki0, ki1);

  // side stream for the ALU-bound PRNG (created once, outside capture;
  // first harness call is the uncaptured correctness run)
  static cudaStream_t s2 = 0;
  static cudaEvent_t ev_fork = 0, ev_join = 0;
  if (!s2){
    cudaStreamCreateWithFlags(&s2, cudaStreamNonBlocking);
    cudaEventCreateWithFlags(&ev_fork, cudaEventDisableTiming);
    cudaEventCreateWithFlags(&ev_join, cudaEventDisableTiming);
  }

  // fork: k_angles runs concurrently with tables/stft/mlp
  cudaEventRecord(ev_fork, 0);
  cudaStreamWaitEvent(s2, ev_fork, 0);
  k_angles<<<(NTOT + 255)/256, 256, 0, s2>>>(kr0, kr1, ki0, ki1);
  cudaEventRecord(ev_join, s2);

  k_tables<<<(2048+L_OLA+NBINS + 255)/256, 256>>>();
  k_stft_lin<<<NPAIR, 256>>>(x);
  k_feats_mlp<<<NFRT/8, 256>>>(x, W1, b1, W2, b2, W3, b3, outc);

  // join before first use of g_ang / g_tprev
  cudaStreamWaitEvent(0, ev_join, 0);

  for (int it = 0; it < 4; ++it){
    k_ifft_frames<<<NPAIR, 256>>>();
    k_ola<<<(BATCH*T_LEN)/256, 256>>>(out, 0);
    k_stft_update<<<NPAIR, 256>>>();
  }
  k_ifft_frames<<<NPAIR, 256>>>();
  k_ola<<<(BATCH*T_LEN)/256, 256>>>(out, 1);
}

// round 6
// speedup vs baseline: 1.0172x; 1.0172x over previous
#include <cuda_runtime.h>
#include <math.h>
#include <stdint.h>

#define BATCH 16
#define T_LEN 131072
#define HOP 256
#define NFFT 2048
#define NBINS 1025
#define NFR 513
#define NFRT (BATCH*NFR)          /* 8208 */
#define NPT 257                    /* frame pairs per batch (last has no B) */
#define NPAIR (BATCH*NPT)          /* 4112 */
#define NMELS 80
#define MIN_P 32
#define NLAG 224
#define L_OLA 133120               /* NFFT + HOP*(NFR-1) */
#define NTOT (BATCH*NBINS*NFR)     /* 8413200 */
#define MOM (0.99f/1.99f)

#define PAD(i) ((i) + ((i)>>3))
#define ZLEN 2304                  /* PAD(2047)=2302 */

// ---------------- scratch (static device globals; no allocs) ----------------
__device__ float  g_win[NFFT];
__device__ float  g_env[L_OLA];
__device__ int    g_fbi[NBINS];
__device__ float2 g_fbw[NBINS];
__device__ float  g_lin[NFRT*NBINS];
__device__ float2 g_ang[NFRT*NBINS];
__device__ float2 g_tprev[NFRT*NBINS];
__device__ float  g_frames[NFRT*NFFT];
__device__ float  g_inv[BATCH*T_LEN];

// ---------------- threefry-2x32-20 (matches jax partitionable) ----------------
__host__ __device__ __forceinline__ unsigned rotl32(unsigned x, int r){ return (x<<r)|(x>>(32-r)); }
__host__ __device__ inline void tf2x32(unsigned k0,unsigned k1,unsigned x0,unsigned x1,unsigned&o0,unsigned&o1){
  unsigned k2 = k0^k1^0x1BD11BDAu;
  x0+=k0; x1+=k1;
  #define TFR(r) { x0+=x1; x1=rotl32(x1,(r)); x1^=x0; }
  TFR(13) TFR(15) TFR(26) TFR(6)  x0+=k1; x1+=k2+1u;
  TFR(17) TFR(29) TFR(16) TFR(24) x0+=k2; x1+=k0+2u;
  TFR(13) TFR(15) TFR(26) TFR(6)  x0+=k0; x1+=k1+3u;
  TFR(17) TFR(29) TFR(16) TFR(24) x0+=k1; x1+=k2+4u;
  TFR(13) TFR(15) TFR(26) TFR(6)  x0+=k2; x1+=k0+5u;
  #undef TFR
  o0=x0; o1=x1;
}
__device__ __forceinline__ float u01(unsigned bits){
  return __uint_as_float((bits>>9) | 0x3f800000u) - 1.0f;
}
__device__ __forceinline__ int refl(int j, int n){
  if (j < 0) j = -j;
  if (j >= n) j = 2*n - 2 - j;
  return j;
}

// ---------------- register radix-8 DFT (DIF), DIR=+1 fwd / -1 inv ----------------
template<int DIR>
__device__ __forceinline__ void dft8(float* ar, float* ai){
  const float r2 = 0.70710678118654752f;
  const float d = (float)DIR;
  float t0r=ar[0]+ar[4], t0i=ai[0]+ai[4];
  float t4r=ar[0]-ar[4], t4i=ai[0]-ai[4];
  float t1r=ar[1]+ar[5], t1i=ai[1]+ai[5];
  float t5r=ar[1]-ar[5], t5i=ai[1]-ai[5];
  float t2r=ar[2]+ar[6], t2i=ai[2]+ai[6];
  float t6r=ar[2]-ar[6], t6i=ai[2]-ai[6];
  float t3r=ar[3]+ar[7], t3i=ai[3]+ai[7];
  float t7r=ar[3]-ar[7], t7i=ai[3]-ai[7];
  { float a=t5r,b=t5i; t5r=r2*(a+d*b); t5i=r2*(b-d*a); }      // *w8^1
  { float a=t6r,b=t6i; t6r=d*b; t6i=-d*a; }                   // *w8^2 = -i*d
  { float a=t7r,b=t7i; t7r=r2*(d*b-a); t7i=-r2*(b+d*a); }     // *w8^3
  float u0r=t0r+t2r,u0i=t0i+t2i, u1r=t0r-t2r,u1i=t0i-t2i;
  float u2r=t1r+t3r,u2i=t1i+t3i, u3r=t1r-t3r,u3i=t1i-t3i;
  float vr=d*u3i, vi=-d*u3r;
  ar[0]=u0r+u2r; ai[0]=u0i+u2i;
  ar[4]=u0r-u2r; ai[4]=u0i-u2i;
  ar[2]=u1r+vr;  ai[2]=u1i+vi;
  ar[6]=u1r-vr;  ai[6]=u1i-vi;
  u0r=t4r+t6r; u0i=t4i+t6i; u1r=t4r-t6r; u1i=t4i-t6i;
  u2r=t5r+t7r; u2i=t5i+t7i; u3r=t5r-t7r; u3i=t5i-t7i;
  vr=d*u3i; vi=-d*u3r;
  ar[1]=u0r+u2r; ai[1]=u0i+u2i;
  ar[5]=u0r-u2r; ai[5]=u0i-u2i;
  ar[3]=u1r+vr;  ai[3]=u1i+vi;
  ar[7]=u1r-vr;  ai[7]=u1i-vi;
}

// ---------------- size-2048 Stockham FFT, radix 8*8*8*4, single SoA buffer ----------------
template<int DIR>
__device__ __forceinline__ void fft2048_r8(float* Zr, float* Zi, int tid){
  #pragma unroll
  for (int st = 0; st < 3; ++st){
    const int s = (st==0) ? 1 : (st==1) ? 8 : 64;
    int q = tid & (s-1);
    int ps = tid - q;
    float ar[8], ai[8];
    #pragma unroll
    for (int j=0;j<8;++j){ int idx = tid + (j<<8); ar[j]=Zr[PAD(idx)]; ai[j]=Zi[PAD(idx)]; }
    __syncthreads();
    dft8<DIR>(ar, ai);
    float sn, cs;
    sincospif((float)ps * (1.0f/1024.0f), &sn, &cs);
    float w1r = cs, w1i = -(float)DIR * sn;
    float wr = w1r, wi = w1i;
    int base = q + (ps<<3);
    Zr[PAD(base)] = ar[0]; Zi[PAD(base)] = ai[0];
    #pragma unroll
    for (int k=1;k<8;++k){
      float br = ar[k]*wr - ai[k]*wi;
      float bi = ar[k]*wi + ai[k]*wr;
      int idx = base + s*k;
      Zr[PAD(idx)] = br; Zi[PAD(idx)] = bi;
      float nwr = wr*w1r - wi*w1i; wi = wr*w1i + wi*w1r; wr = nwr;
    }
    __syncthreads();
  }
  float cr[8], ci[8];
  #pragma unroll
  for (int h=0; h<2; ++h){
    int i = tid + (h<<8);
    #pragma unroll
    for (int j=0;j<4;++j){ int idx = i + (j<<9); cr[h*4+j]=Zr[PAD(idx)]; ci[h*4+j]=Zi[PAD(idx)]; }
  }
  __syncthreads();
  const float d = (float)DIR;
  #pragma unroll
  for (int h=0;h<2;++h){
    int i = tid + (h<<8);
    float u0r=cr[h*4]+cr[h*4+2], u0i=ci[h*4]+ci[h*4+2];
    float u1r=cr[h*4]-cr[h*4+2], u1i=ci[h*4]-ci[h*4+2];
    float u2r=cr[h*4+1]+cr[h*4+3], u2i=ci[h*4+1]+ci[h*4+3];
    float u3r=cr[h*4+1]-cr[h*4+3], u3i=ci[h*4+1]-ci[h*4+3];
    float vr=d*u3i, vi=-d*u3r;
    Zr[PAD(i)]      = u0r+u2r; Zi[PAD(i)]      = u0i+u2i;
    Zr[PAD(i+512)]  = u1r+vr;  Zi[PAD(i+512)]  = u1i+vi;
    Zr[PAD(i+1024)] = u0r-u2r; Zi[PAD(i+1024)] = u0i-u2i;
    Zr[PAD(i+1536)] = u1r-vr;  Zi[PAD(i+1536)] = u1i-vi;
  }
  __syncthreads();
}

// ---------------- init tables ----------------
__global__ void k_tables(){
  int idx = blockIdx.x*blockDim.x + threadIdx.x;
  if (idx < 2048){
    g_win[idx] = (float)(0.5 - 0.5*cos(2.0*M_PI*(double)idx/2048.0));
  } else if (idx < 2048+L_OLA){
    int i = idx - 2048;
    int flo = (i - 1792) >> 8; if (flo < 0) flo = 0;
    int fhi = i >> 8;          if (fhi > NFR-1) fhi = NFR-1;
    double acc = 0.0;
    for (int f = flo; f <= fhi; ++f){
      int n = i - 256*f;
      double w = 0.5 - 0.5*cos(2.0*M_PI*(double)n/2048.0);
      acc += w*w;
    }
    g_env[i] = (float)acc;
  } else {
    int f = idx - 2048 - L_OLA;
    if (f < NBINS){
      double mmax = 2595.0*log10(1.0 + 8000.0/700.0);
      double freq = (double)f * 8000.0/1024.0;
      int first = -1; float w0 = 0.f, w1 = 0.f;
      for (int m = 0; m < NMELS; ++m){
        double fp0 = 700.0*(pow(10.0, (double)(m  )*mmax/81.0/2595.0) - 1.0);
        double fp1 = 700.0*(pow(10.0, (double)(m+1)*mmax/81.0/2595.0) - 1.0);
        double fp2 = 700.0*(pow(10.0, (double)(m+2)*mmax/81.0/2595.0) - 1.0);
        double dn = (freq - fp0)/(fp1 - fp0);
        double up = (fp2 - freq)/(fp2 - fp1);
        double v = dn < up ? dn : up;
        if (v > 0.0){
          if (first < 0){ first = m; w0 = (float)v; }
          else w1 = (float)v;
        }
      }
      g_fbi[f] = first;
      g_fbw[f] = make_float2(w0, w1);
    }
  }
}

// ---------------- initial random phases (coalesced writes; counter computed) ----------------
__global__ void k_angles(unsigned kr0,unsigned kr1,unsigned ki0,unsigned ki1){
  int m = blockIdx.x*blockDim.x + threadIdx.x;   // m indexes (b,t,f) storage layout
  if (m >= NTOT) return;
  int f  = m % NBINS;
  int bt = m / NBINS;
  int t  = bt % NFR;
  int b  = bt / NFR;
  unsigned e = ((unsigned)(b*NBINS + f))*((unsigned)NFR) + (unsigned)t; // jax (B,F,T) linear idx
  unsigned r0,r1,i0,i1;
  tf2x32(kr0,kr1, 0u, e, r0,r1);
  tf2x32(ki0,ki1, 0u, e, i0,i1);
  g_ang[m]   = make_float2(u01(r0^r1), u01(i0^i1));
  g_tprev[m] = make_float2(0.f, 0.f);
}

// ---------------- f0 / loudness (1 frame per warp) + MLP (8 frames per block) ----------------
__global__ void k_feats_mlp(const float* __restrict__ x,
                            const float* __restrict__ W1, const float* __restrict__ b1,
                            const float* __restrict__ W2, const float* __restrict__ b2,
                            const float* __restrict__ W3, const float* __restrict__ b3,
                            float* __restrict__ outc){
  __shared__ float s[8][768];          // 512 window + zero tail (lag reach 734)
  __shared__ float h1s[8*256];
  __shared__ float h2s[8*256];
  __shared__ float feat[8][2];
  int tid = threadIdx.x;
  int w = tid >> 5, lane = tid & 31;
  int base = blockIdx.x * 8;

  // --- per-warp front end: one frame per warp, zero block syncs ---
  {
    int fr = base + w;
    int b = fr / NFR, t = fr % NFR;
    const float* xb = x + (size_t)b * T_LEN;
    for (int k = lane; k < 512; k += 32)
      s[w][k] = xb[refl(t*HOP + k - 256, T_LEN)];
    for (int k = 512 + lane; k < 768; k += 32)
      s[w][k] = 0.f;
    __syncwarp();
    // sum of squares (warp reduce)
    float ss = 0.f;
    for (int k = lane; k < 512; k += 32){ float v = s[w][k]; ss += v*v; }
    #pragma unroll
    for (int o = 16; o; o >>= 1) ss += __shfl_xor_sync(0xffffffffu, ss, o);
    // autocorr: 7 lags per lane (lag = 32+lane+32*kk), t2-outer so s[t2] broadcast once
    float acc[7];
    #pragma unroll
    for (int kk = 0; kk < 7; ++kk) acc[kk] = 0.f;
    int la0 = MIN_P + lane;
    for (int t2 = 0; t2 < 480; ++t2){
      float v0 = s[w][t2];
      int ix = t2 + la0;
      #pragma unroll
      for (int kk = 0; kk < 7; ++kk)
        acc[kk] += v0 * s[w][ix + (kk<<5)];
    }
    float best = -1e30f; int bi = 0;
    #pragma unroll
    for (int kk = 0; kk < 7; ++kk){
      if (acc[kk] > best){ best = acc[kk]; bi = lane + (kk<<5); }  // strict > keeps first
    }
    #pragma unroll
    for (int o = 16; o; o >>= 1){
      float vo = __shfl_xor_sync(0xffffffffu, best, o);
      int   io = __shfl_xor_sync(0xffffffffu, bi,   o);
      if (vo > best || (vo == best && io < bi)){ best = vo; bi = io; }
    }
    if (lane == 0){
      float period = (float)(bi + MIN_P);
      float f0 = 16000.0f/(period + 1e-8f);
      f0 = fminf(fmaxf(f0, 50.0f), 500.0f);
      float loud = 20.0f*log10f(sqrtf(ss/512.0f) + 1e-8f);
      feat[w][0] = f0; feat[w][1] = loud;
    }
  }
  __syncthreads();

  // --- MLP: all 256 threads cooperate across 8 frames ---
  #pragma unroll
  for (int u = 0; u < 8; ++u){
    float f0 = feat[u][0], ld = feat[u][1];
    float z = f0*W1[tid] + ld*W1[256+tid] + b1[tid];
    h1s[u*256+tid] = z > 0.f ? z : expm1f(z);
  }
  __syncthreads();
  float acc[8];
  #pragma unroll
  for (int u = 0; u < 8; ++u) acc[u] = b2[tid];
  for (int k = 0; k < 256; ++k){
    float wv = W2[k*256 + tid];
    #pragma unroll
    for (int u = 0; u < 8; ++u) acc[u] += h1s[u*256+k]*wv;
  }
  #pragma unroll
  for (int u = 0; u < 8; ++u){
    float z = acc[u];
    h2s[u*256+tid] = z > 0.f ? z : expm1f(z);
  }
  __syncthreads();
  int o = tid & 63;
  for (int pass = 0; pass < 2; ++pass){
    int u = (tid >> 6) + pass*4;
    float a3 = b3[o];
    for (int k = 0; k < 256; ++k) a3 += h2s[u*256+k]*W3[k*64 + o];
    int fr = base + u;
    outc[(size_t)fr*64 + o] = a3;
  }
}

// ---------------- STFT (2 frames packed) -> mag -> mel (sparse scatter) -> linear ----------------
__global__ void k_stft_lin(const float* __restrict__ x){
  __shared__ float Zr[ZLEN], Zi[ZLEN];
  __shared__ float mel[2][NMELS];
  int tid = threadIdx.x;
  int pb = blockIdx.x;
  int b = pb / NPT, pt = pb % NPT;
  int t0 = 2*pt;
  bool hasB = (t0 + 1 < NFR);
  int fr0 = b*NFR + t0;
  const float* xb = x + (size_t)b * T_LEN;
  for (int k = tid; k < 2048; k += 256){
    float w = g_win[k];
    Zr[PAD(k)] = xb[refl(t0*HOP + k - 1024, T_LEN)] * w;
    float vb = 0.f;
    if (hasB) vb = xb[refl((t0+1)*HOP + k - 1024, T_LEN)] * w;
    Zi[PAD(k)] = vb;
  }
  if (tid < 2*NMELS) ((float*)mel)[tid] = 0.f;
  __syncthreads();
  fft2048_r8<1>(Zr, Zi, tid);
  for (int k = tid; k <= 1024; k += 256){
    int m = (2048 - k) & 2047;
    float zkr=Zr[PAD(k)], zki=Zi[PAD(k)], zmr=Zr[PAD(m)], zmi=Zi[PAD(m)];
    float far_ = 0.5f*(zkr + zmr), fai = 0.5f*(zki - zmi);
    float dr = zkr - zmr, di = zki + zmi;
    float fbr = 0.5f*di, fbi = -0.5f*dr;
    float maga = sqrtf(far_*far_ + fai*fai);
    float magb = sqrtf(fbr*fbr + fbi*fbi);
    int i = g_fbi[k];
    float2 w = g_fbw[k];
    if (i >= 0){
      atomicAdd(&mel[0][i], maga*w.x);
      atomicAdd(&mel[1][i], magb*w.x);
      if (w.y != 0.f && i+1 < NMELS){
        atomicAdd(&mel[0][i+1], maga*w.y);
        atomicAdd(&mel[1][i+1], magb*w.y);
      }
    }
  }
  __syncthreads();
  for (int f = tid; f <= 1024; f += 256){
    float src = fmaxf((f + 0.5f)*(80.0f/1025.0f) - 0.5f, 0.0f);
    int i0 = (int)floorf(src); if (i0 > 79) i0 = 79; if (i0 < 0) i0 = 0;
    int i1 = i0 + 1; if (i1 > 79) i1 = 79;
    float w = src - (float)i0;
    g_lin[(size_t)fr0*NBINS + f] = (1.0f - w)*mel[0][i0] + w*mel[0][i1];
    if (hasB) g_lin[(size_t)(fr0+1)*NBINS + f] = (1.0f - w)*mel[1][i0] + w*mel[1][i1];
  }
}

// ---------------- inverse FFT of spec*angles (2 frames packed) -> windowed frames ----------------
__global__ void k_ifft_frames(){
  __shared__ float Zr[ZLEN], Zi[ZLEN];
  int tid = threadIdx.x;
  int pb = blockIdx.x;
  int b = pb / NPT, pt = pb % NPT;
  int t0 = 2*pt;
  bool hasB = (t0 + 1 < NFR);
  int fr0 = b*NFR + t0;
  const float*  lin0 = g_lin + (size_t)fr0*NBINS;
  const float2* ang0 = g_ang + (size_t)fr0*NBINS;
  for (int k = tid; k <= 1024; k += 256){
    // irfft ignores Im at DC/Nyquist -> zero so each half-spectrum is Hermitian
    float msk = (k == 0 || k == 1024) ? 0.f : 1.f;
    float  L = lin0[k];
    float2 a = ang0[k];
    float ar_ = L*a.x, ai_ = L*a.y*msk;
    float br_ = 0.f, bi_ = 0.f;
    if (hasB){
      float Lb = lin0[NBINS + k];
      float2 ab = ang0[NBINS + k];
      br_ = Lb*ab.x; bi_ = Lb*ab.y*msk;
    }
    Zr[PAD(k)] = ar_ - bi_;
    Zi[PAD(k)] = ai_ + br_;
    if (k > 0 && k < 1024){
      int mm = 2048 - k;
      Zr[PAD(mm)] = ar_ + bi_;
      Zi[PAD(mm)] = br_ - ai_;
    }
  }
  __syncthreads();
  fft2048_r8<-1>(Zr, Zi, tid);
  float* oa = g_frames + (size_t)fr0 * 2048;
  for (int n = tid; n < 2048; n += 256){
    float w = g_win[n] * (1.0f/2048.0f);
    oa[n] = Zr[PAD(n)] * w;
    if (hasB) oa[2048 + n] = Zi[PAD(n)] * w;
  }
}

// ---------------- overlap-add gather (deterministic) ----------------
__global__ void k_ola(float* __restrict__ out_final, int is_final){
  int gid = blockIdx.x*blockDim.x + threadIdx.x;
  if (gid >= BATCH*T_LEN) return;
  int b = gid >> 17;
  int i = gid & (T_LEN - 1);
  int pos = i + 1024;
  int flo = (pos - 1792) >> 8; if (flo < 0) flo = 0;
  int fhi = pos >> 8;          if (fhi > NFR-1) fhi = NFR-1;
  const float* fbuf = g_frames + (size_t)b * NFR * 2048;
  float acc = 0.f;
  for (int f = flo; f <= fhi; ++f)
    acc += fbuf[(size_t)f*2048 + (pos - (f<<8))];
  float e = g_env[pos];
  float r = acc / (e > 1e-11f ? e : 1.0f);
  if (is_final) out_final[gid] = r;
  else          g_inv[gid] = r;
}

// ---------------- STFT of inv (2 frames packed) + phase update ----------------
__global__ void k_stft_update(){
  __shared__ float Zr[ZLEN], Zi[ZLEN];
  int tid = threadIdx.x;
  int pb = blockIdx.x;
  int b = pb / NPT, pt = pb % NPT;
  int t0 = 2*pt;
  bool hasB = (t0 + 1 < NFR);
  int fr0 = b*NFR + t0;
  const float* xb = g_inv + (size_t)b * T_LEN;
  for (int k = tid; k < 2048; k += 256){
    float w = g_win[k];
    Zr[PAD(k)] = xb[refl(t0*HOP + k - 1024, T_LEN)] * w;
    float vb = 0.f;
    if (hasB) vb = xb[refl((t0+1)*HOP + k - 1024, T_LEN)] * w;
    Zi[PAD(k)] = vb;
  }
  __syncthreads();
  fft2048_r8<1>(Zr, Zi, tid);
  float2* angp = g_ang   + (size_t)fr0*NBINS;
  float2* tpp  = g_tprev + (size_t)fr0*NBINS;
  for (int k = tid; k <= 1024; k += 256){
    int m = (2048 - k) & 2047;
    float zkr=Zr[PAD(k)], zki=Zi[PAD(k)], zmr=Zr[PAD(m)], zmi=Zi[PAD(m)];
    float rar = 0.5f*(zkr + zmr), rai = 0.5f*(zki - zmi);
    float dr = zkr - zmr, di = zki + zmi;
    float rbr = 0.5f*di, rbi = -0.5f*dr;
    float2 tp = tpp[k];
    float ax = rar - MOM*tp.x, ay = rai - MOM*tp.y;
    float mg = sqrtf(ax*ax + ay*ay) + 1e-16f;
    angp[k] = make_float2(ax/mg, ay/mg);
    tpp[k]  = make_float2(rar, rai);
    if (hasB){
      float2 tpb = tpp[NBINS + k];
      float bx = rbr - MOM*tpb.x, by = rbi - MOM*tpb.y;
      float mb = sqrtf(bx*bx + by*by) + 1e-16f;
      angp[NBINS + k] = make_float2(bx/mb, by/mb);
      tpp[NBINS + k]  = make_float2(rbr, rbi);
    }
  }
}

// ---------------- launch (single stream, serial) ----------------
extern "C" void kernel_launch(void* const* d_in, const int* in_sizes, int n_in,
                              void* d_out, int out_size){
  const float* x  = (const float*)d_in[0];
  const float* W1 = (const float*)d_in[1];
  const float* b1 = (const float*)d_in[2];
  const float* W2 = (const float*)d_in[3];
  const float* b2 = (const float*)d_in[4];
  const float* W3 = (const float*)d_in[5];
  const float* b3 = (const float*)d_in[6];
  float* out  = (float*)d_out;
  float* outc = out + (size_t)BATCH*T_LEN;

  // jax.random.key(42)=(0,42); partitionable split:
  // kr = threefry((0,42),(0,0)), ki = threefry((0,42),(0,1))
  unsigned kr0,kr1,ki0,ki1;
  tf2x32(0u, 42u, 0u, 0u, kr0, kr1);
  tf2x32(0u, 42u, 0u, 1u, ki0, ki1);

  k_tables<<<(2048+L_OLA+NBINS + 255)/256, 256>>>();
  k_angles<<<(NTOT + 255)/256, 256>>>(kr0, kr1, ki0, ki1);
  k_feats_mlp<<<NFRT/8, 256>>>(x, W1, b1, W2, b2, W3, b3, outc);
  k_stft_lin<<<NPAIR, 256>>>(x);
  for (int it = 0; it < 4; ++it){
    k_ifft_frames<<<NPAIR, 256>>>();
    k_ola<<<(BATCH*T_LEN)/256, 256>>>(out, 0);
    k_stft_update<<<NPAIR, 256>>>();
  }
  k_ifft_frames<<<NPAIR, 256>>>();
  k_ola<<<(BATCH*T_LEN)/256, 256>>>(out, 1);
}

// round 7
// speedup vs baseline: 2.7768x; 2.7299x over previous
#include <cuda_runtime.h>
#include <math.h>
#include <stdint.h>

#define BATCH 16
#define T_LEN 131072
#define HOP 256
#define NFFT 2048
#define NBINS 1025
#define NFR 513
#define NFRT (BATCH*NFR)          /* 8208 */
#define NPT 257                    /* frame pairs per batch (last has no B) */
#define NPAIR (BATCH*NPT)          /* 4112 */
#define NMELS 80
#define MIN_P 32
#define NLAG 224
#define L_OLA 133120               /* NFFT + HOP*(NFR-1) */
#define NTOT (BATCH*NBINS*NFR)     /* 8413200 */
#define MOM (0.99f/1.99f)

#define PAD(i) ((i) + ((i)>>3))
#define ZLEN 2304                  /* PAD(2047)=2302 */

// ---------------- scratch (static device globals; no allocs) ----------------
__device__ float  g_fpts[NMELS+2];
__device__ float  g_win[NFFT];
__device__ float  g_env[L_OLA];
__device__ int    g_fbi[NBINS];
__device__ float2 g_fbw[NBINS];
__device__ float  g_lin[NFRT*NBINS];
__device__ float2 g_ang[NFRT*NBINS];
__device__ float2 g_tprev[NFRT*NBINS];
__device__ float  g_frames[NFRT*NFFT];
__device__ float  g_inv[BATCH*T_LEN];

// ---------------- threefry-2x32-20 (matches jax partitionable) ----------------
__host__ __device__ __forceinline__ unsigned rotl32(unsigned x, int r){ return (x<<r)|(x>>(32-r)); }
__host__ __device__ inline void tf2x32(unsigned k0,unsigned k1,unsigned x0,unsigned x1,unsigned&o0,unsigned&o1){
  unsigned k2 = k0^k1^0x1BD11BDAu;
  x0+=k0; x1+=k1;
  #define TFR(r) { x0+=x1; x1=rotl32(x1,(r)); x1^=x0; }
  TFR(13) TFR(15) TFR(26) TFR(6)  x0+=k1; x1+=k2+1u;
  TFR(17) TFR(29) TFR(16) TFR(24) x0+=k2; x1+=k0+2u;
  TFR(13) TFR(15) TFR(26) TFR(6)  x0+=k0; x1+=k1+3u;
  TFR(17) TFR(29) TFR(16) TFR(24) x0+=k1; x1+=k2+4u;
  TFR(13) TFR(15) TFR(26) TFR(6)  x0+=k2; x1+=k0+5u;
  #undef TFR
  o0=x0; o1=x1;
}
__device__ __forceinline__ float u01(unsigned bits){
  return __uint_as_float((bits>>9) | 0x3f800000u) - 1.0f;
}
__device__ __forceinline__ int refl(int j, int n){
  if (j < 0) j = -j;
  if (j >= n) j = 2*n - 2 - j;
  return j;
}

// ---------------- register radix-8 DFT (DIF), DIR=+1 fwd / -1 inv ----------------
template<int DIR>
__device__ __forceinline__ void dft8(float* ar, float* ai){
  const float r2 = 0.70710678118654752f;
  const float d = (float)DIR;
  float t0r=ar[0]+ar[4], t0i=ai[0]+ai[4];
  float t4r=ar[0]-ar[4], t4i=ai[0]-ai[4];
  float t1r=ar[1]+ar[5], t1i=ai[1]+ai[5];
  float t5r=ar[1]-ar[5], t5i=ai[1]-ai[5];
  float t2r=ar[2]+ar[6], t2i=ai[2]+ai[6];
  float t6r=ar[2]-ar[6], t6i=ai[2]-ai[6];
  float t3r=ar[3]+ar[7], t3i=ai[3]+ai[7];
  float t7r=ar[3]-ar[7], t7i=ai[3]-ai[7];
  { float a=t5r,b=t5i; t5r=r2*(a+d*b); t5i=r2*(b-d*a); }      // *w8^1
  { float a=t6r,b=t6i; t6r=d*b; t6i=-d*a; }                   // *w8^2 = -i*d
  { float a=t7r,b=t7i; t7r=r2*(d*b-a); t7i=-r2*(b+d*a); }     // *w8^3
  float u0r=t0r+t2r,u0i=t0i+t2i, u1r=t0r-t2r,u1i=t0i-t2i;
  float u2r=t1r+t3r,u2i=t1i+t3i, u3r=t1r-t3r,u3i=t1i-t3i;
  float vr=d*u3i, vi=-d*u3r;
  ar[0]=u0r+u2r; ai[0]=u0i+u2i;
  ar[4]=u0r-u2r; ai[4]=u0i-u2i;
  ar[2]=u1r+vr;  ai[2]=u1i+vi;
  ar[6]=u1r-vr;  ai[6]=u1i-vi;
  u0r=t4r+t6r; u0i=t4i+t6i; u1r=t4r-t6r; u1i=t4i-t6i;
  u2r=t5r+t7r; u2i=t5i+t7i; u3r=t5r-t7r; u3i=t5i-t7i;
  vr=d*u3i; vi=-d*u3r;
  ar[1]=u0r+u2r; ai[1]=u0i+u2i;
  ar[5]=u0r-u2r; ai[5]=u0i-u2i;
  ar[3]=u1r+vr;  ai[3]=u1i+vi;
  ar[7]=u1r-vr;  ai[7]=u1i-vi;
}

// ---------------- size-2048 Stockham FFT, radix 8*8*8*4, single SoA buffer ----------------
template<int DIR>
__device__ __forceinline__ void fft2048_r8(float* Zr, float* Zi, int tid){
  #pragma unroll
  for (int st = 0; st < 3; ++st){
    const int s = (st==0) ? 1 : (st==1) ? 8 : 64;
    int q = tid & (s-1);
    int ps = tid - q;
    float ar[8], ai[8];
    #pragma unroll
    for (int j=0;j<8;++j){ int idx = tid + (j<<8); ar[j]=Zr[PAD(idx)]; ai[j]=Zi[PAD(idx)]; }
    __syncthreads();
    dft8<DIR>(ar, ai);
    float sn, cs;
    sincospif((float)ps * (1.0f/1024.0f), &sn, &cs);
    float w1r = cs, w1i = -(float)DIR * sn;
    float wr = w1r, wi = w1i;
    int base = q + (ps<<3);
    Zr[PAD(base)] = ar[0]; Zi[PAD(base)] = ai[0];
    #pragma unroll
    for (int k=1;k<8;++k){
      float br = ar[k]*wr - ai[k]*wi;
      float bi = ar[k]*wi + ai[k]*wr;
      int idx = base + s*k;
      Zr[PAD(idx)] = br; Zi[PAD(idx)] = bi;
      float nwr = wr*w1r - wi*w1i; wi = wr*w1i + wi*w1r; wr = nwr;
    }
    __syncthreads();
  }
  float cr[8], ci[8];
  #pragma unroll
  for (int h=0; h<2; ++h){
    int i = tid + (h<<8);
    #pragma unroll
    for (int j=0;j<4;++j){ int idx = i + (j<<9); cr[h*4+j]=Zr[PAD(idx)]; ci[h*4+j]=Zi[PAD(idx)]; }
  }
  __syncthreads();
  const float d = (float)DIR;
  #pragma unroll
  for (int h=0;h<2;++h){
    int i = tid + (h<<8);
    float u0r=cr[h*4]+cr[h*4+2], u0i=ci[h*4]+ci[h*4+2];
    float u1r=cr[h*4]-cr[h*4+2], u1i=ci[h*4]-ci[h*4+2];
    float u2r=cr[h*4+1]+cr[h*4+3], u2i=ci[h*4+1]+ci[h*4+3];
    float u3r=cr[h*4+1]-cr[h*4+3], u3i=ci[h*4+1]-ci[h*4+3];
    float vr=d*u3i, vi=-d*u3r;
    Zr[PAD(i)]      = u0r+u2r; Zi[PAD(i)]      = u0i+u2i;
    Zr[PAD(i+512)]  = u1r+vr;  Zi[PAD(i+512)]  = u1i+vi;
    Zr[PAD(i+1024)] = u0r-u2r; Zi[PAD(i+1024)] = u0i-u2i;
    Zr[PAD(i+1536)] = u1r-vr;  Zi[PAD(i+1536)] = u1i-vi;
  }
  __syncthreads();
}

// ---------------- mel breakpoints (82 double pows total, once) ----------------
__global__ void k_fpts(){
  int m = threadIdx.x;
  if (m < NMELS+2){
    double mmax = 2595.0*log10(1.0 + 8000.0/700.0);
    g_fpts[m] = (float)(700.0*(pow(10.0, (double)m*mmax/81.0/2595.0) - 1.0));
  }
}

// ---------------- init tables (all float, no pow) ----------------
__global__ void k_tables(){
  int idx = blockIdx.x*blockDim.x + threadIdx.x;
  if (idx < 2048){
    g_win[idx] = 0.5f - 0.5f*cospif((float)idx * (1.0f/1024.0f));
  } else if (idx < 2048+L_OLA){
    int i = idx - 2048;
    int flo = (i - 1792) >> 8; if (flo < 0) flo = 0;
    int fhi = i >> 8;          if (fhi > NFR-1) fhi = NFR-1;
    float acc = 0.f;
    for (int f = flo; f <= fhi; ++f){
      int n = i - 256*f;
      float w = 0.5f - 0.5f*cospif((float)n * (1.0f/1024.0f));
      acc += w*w;
    }
    g_env[i] = acc;
  } else {
    int f = idx - 2048 - L_OLA;
    if (f < NBINS){
      float freq = (float)f * (8000.0f/1024.0f);
      int first = -1; float w0 = 0.f, w1 = 0.f;
      #pragma unroll 4
      for (int m = 0; m < NMELS; ++m){
        float fp0 = g_fpts[m], fp1 = g_fpts[m+1], fp2 = g_fpts[m+2];
        float dn = (freq - fp0)/(fp1 - fp0);
        float up = (fp2 - freq)/(fp2 - fp1);
        float v = fminf(dn, up);
        if (v > 0.f){
          if (first < 0){ first = m; w0 = v; }
          else w1 = v;
        }
      }
      g_fbi[f] = first;
      g_fbw[f] = make_float2(w0, w1);
    }
  }
}

// ---------------- initial random phases (coalesced writes; counter computed) ----------------
__global__ void k_angles(unsigned kr0,unsigned kr1,unsigned ki0,unsigned ki1){
  int m = blockIdx.x*blockDim.x + threadIdx.x;   // m indexes (b,t,f) storage layout
  if (m >= NTOT) return;
  int f  = m % NBINS;
  int bt = m / NBINS;
  int t  = bt % NFR;
  int b  = bt / NFR;
  unsigned e = ((unsigned)(b*NBINS + f))*((unsigned)NFR) + (unsigned)t; // jax (B,F,T) linear idx
  unsigned r0,r1,i0,i1;
  tf2x32(kr0,kr1, 0u, e, r0,r1);
  tf2x32(ki0,ki1, 0u, e, i0,i1);
  g_ang[m]   = make_float2(u01(r0^r1), u01(i0^i1));
  g_tprev[m] = make_float2(0.f, 0.f);
}

// ---------------- f0 / loudness (1 frame per warp) + MLP (8 frames per block) ----------------
__global__ void k_feats_mlp(const float* __restrict__ x,
                            const float* __restrict__ W1, const float* __restrict__ b1,
                            const float* __restrict__ W2, const float* __restrict__ b2,
                            const float* __restrict__ W3, const float* __restrict__ b3,
                            float* __restrict__ outc){
  __shared__ float s[8][768];          // 512 window + zero tail (lag reach 734)
  __shared__ float h1s[8*256];
  __shared__ float h2s[8*256];
  __shared__ float feat[8][2];
  int tid = threadIdx.x;
  int w = tid >> 5, lane = tid & 31;
  int base = blockIdx.x * 8;

  // --- per-warp front end: one frame per warp, zero block syncs ---
  {
    int fr = base + w;
    int b = fr / NFR, t = fr % NFR;
    const float* xb = x + (size_t)b * T_LEN;
    for (int k = lane; k < 512; k += 32)
      s[w][k] = xb[refl(t*HOP + k - 256, T_LEN)];
    for (int k = 512 + lane; k < 768; k += 32)
      s[w][k] = 0.f;
    __syncwarp();
    // sum of squares (warp reduce)
    float ss = 0.f;
    for (int k = lane; k < 512; k += 32){ float v = s[w][k]; ss += v*v; }
    #pragma unroll
    for (int o = 16; o; o >>= 1) ss += __shfl_xor_sync(0xffffffffu, ss, o);
    // autocorr: 7 lags per lane (lag = 32+lane+32*kk), t2-outer so s[t2] broadcast once
    float acc[7];
    #pragma unroll
    for (int kk = 0; kk < 7; ++kk) acc[kk] = 0.f;
    int la0 = MIN_P + lane;
    for (int t2 = 0; t2 < 480; ++t2){
      float v0 = s[w][t2];
      int ix = t2 + la0;
      #pragma unroll
      for (int kk = 0; kk < 7; ++kk)
        acc[kk] += v0 * s[w][ix + (kk<<5)];
    }
    float best = -1e30f; int bi = 0;
    #pragma unroll
    for (int kk = 0; kk < 7; ++kk){
      if (acc[kk] > best){ best = acc[kk]; bi = lane + (kk<<5); }  // strict > keeps first
    }
    #pragma unroll
    for (int o = 16; o; o >>= 1){
      float vo = __shfl_xor_sync(0xffffffffu, best, o);
      int   io = __shfl_xor_sync(0xffffffffu, bi,   o);
      if (vo > best || (vo == best && io < bi)){ best = vo; bi = io; }
    }
    if (lane == 0){
      float period = (float)(bi + MIN_P);
      float f0 = 16000.0f/(period + 1e-8f);
      f0 = fminf(fmaxf(f0, 50.0f), 500.0f);
      float loud = 20.0f*log10f(sqrtf(ss/512.0f) + 1e-8f);
      feat[w][0] = f0; feat[w][1] = loud;
    }
  }
  __syncthreads();

  // --- MLP: all 256 threads cooperate across 8 frames ---
  #pragma unroll
  for (int u = 0; u < 8; ++u){
    float f0 = feat[u][0], ld = feat[u][1];
    float z = f0*W1[tid] + ld*W1[256+tid] + b1[tid];
    h1s[u*256+tid] = z > 0.f ? z : expm1f(z);
  }
  __syncthreads();
  float acc[8];
  #pragma unroll
  for (int u = 0; u < 8; ++u) acc[u] = b2[tid];
  for (int k = 0; k < 256; ++k){
    float wv = W2[k*256 + tid];
    #pragma unroll
    for (int u = 0; u < 8; ++u) acc[u] += h1s[u*256+k]*wv;
  }
  #pragma unroll
  for (int u = 0; u < 8; ++u){
    float z = acc[u];
    h2s[u*256+tid] = z > 0.f ? z : expm1f(z);
  }
  __syncthreads();
  int o = tid & 63;
  for (int pass = 0; pass < 2; ++pass){
    int u = (tid >> 6) + pass*4;
    float a3 = b3[o];
    for (int k = 0; k < 256; ++k) a3 += h2s[u*256+k]*W3[k*64 + o];
    int fr = base + u;
    outc[(size_t)fr*64 + o] = a3;
  }
}

// ---------------- STFT (2 frames packed) -> mag -> mel (sparse scatter) -> linear ----------------
__global__ void k_stft_lin(const float* __restrict__ x){
  __shared__ float Zr[ZLEN], Zi[ZLEN];
  __shared__ float mel[2][NMELS];
  int tid = threadIdx.x;
  int pb = blockIdx.x;
  int b = pb / NPT, pt = pb % NPT;
  int t0 = 2*pt;
  bool hasB = (t0 + 1 < NFR);
  int fr0 = b*NFR + t0;
  const float* xb = x + (size_t)b * T_LEN;
  for (int k = tid; k < 2048; k += 256){
    float w = g_win[k];
    Zr[PAD(k)] = xb[refl(t0*HOP + k - 1024, T_LEN)] * w;
    float vb = 0.f;
    if (hasB) vb = xb[refl((t0+1)*HOP + k - 1024, T_LEN)] * w;
    Zi[PAD(k)] = vb;
  }
  if (tid < 2*NMELS) ((float*)mel)[tid] = 0.f;
  __syncthreads();
  fft2048_r8<1>(Zr, Zi, tid);
  for (int k = tid; k <= 1024; k += 256){
    int m = (2048 - k) & 2047;
    float zkr=Zr[PAD(k)], zki=Zi[PAD(k)], zmr=Zr[PAD(m)], zmi=Zi[PAD(m)];
    float far_ = 0.5f*(zkr + zmr), fai = 0.5f*(zki - zmi);
    float dr = zkr - zmr, di = zki + zmi;
    float fbr = 0.5f*di, fbi = -0.5f*dr;
    float maga = sqrtf(far_*far_ + fai*fai);
    float magb = sqrtf(fbr*fbr + fbi*fbi);
    int i = g_fbi[k];
    float2 w = g_fbw[k];
    if (i >= 0){
      atomicAdd(&mel[0][i], maga*w.x);
      atomicAdd(&mel[1][i], magb*w.x);
      if (w.y != 0.f && i+1 < NMELS){
        atomicAdd(&mel[0][i+1], maga*w.y);
        atomicAdd(&mel[1][i+1], magb*w.y);
      }
    }
  }
  __syncthreads();
  for (int f = tid; f <= 1024; f += 256){
    float src = fmaxf((f + 0.5f)*(80.0f/1025.0f) - 0.5f, 0.0f);
    int i0 = (int)floorf(src); if (i0 > 79) i0 = 79; if (i0 < 0) i0 = 0;
    int i1 = i0 + 1; if (i1 > 79) i1 = 79;
    float w = src - (float)i0;
    g_lin[(size_t)fr0*NBINS + f] = (1.0f - w)*mel[0][i0] + w*mel[0][i1];
    if (hasB) g_lin[(size_t)(fr0+1)*NBINS + f] = (1.0f - w)*mel[1][i0] + w*mel[1][i1];
  }
}

// ---------------- inverse FFT of spec*angles (2 frames packed) -> windowed frames ----------------
__global__ void k_ifft_frames(){
  __shared__ float Zr[ZLEN], Zi[ZLEN];
  int tid = threadIdx.x;
  int pb = blockIdx.x;
  int b = pb / NPT, pt = pb % NPT;
  int t0 = 2*pt;
  bool hasB = (t0 + 1 < NFR);
  int fr0 = b*NFR + t0;
  const float*  lin0 = g_lin + (size_t)fr0*NBINS;
  const float2* ang0 = g_ang + (size_t)fr0*NBINS;
  for (int k = tid; k <= 1024; k += 256){
    // irfft ignores Im at DC/Nyquist -> zero so each half-spectrum is Hermitian
    float msk = (k == 0 || k == 1024) ? 0.f : 1.f;
    float  L = lin0[k];
    float2 a = ang0[k];
    float ar_ = L*a.x, ai_ = L*a.y*msk;
    float br_ = 0.f, bi_ = 0.f;
    if (hasB){
      float Lb = lin0[NBINS + k];
      float2 ab = ang0[NBINS + k];
      br_ = Lb*ab.x; bi_ = Lb*ab.y*msk;
    }
    Zr[PAD(k)] = ar_ - bi_;
    Zi[PAD(k)] = ai_ + br_;
    if (k > 0 && k < 1024){
      int mm = 2048 - k;
      Zr[PAD(mm)] = ar_ + bi_;
      Zi[PAD(mm)] = br_ - ai_;
    }
  }
  __syncthreads();
  fft2048_r8<-1>(Zr, Zi, tid);
  float* oa = g_frames + (size_t)fr0 * 2048;
  for (int n = tid; n < 2048; n += 256){
    float w = g_win[n] * (1.0f/2048.0f);
    oa[n] = Zr[PAD(n)] * w;
    if (hasB) oa[2048 + n] = Zi[PAD(n)] * w;
  }
}

// ---------------- overlap-add gather (deterministic) ----------------
__global__ void k_ola(float* __restrict__ out_final, int is_final){
  int gid = blockIdx.x*blockDim.x + threadIdx.x;
  if (gid >= BATCH*T_LEN) return;
  int b = gid >> 17;
  int i = gid & (T_LEN - 1);
  int pos = i + 1024;
  int flo = (pos - 1792) >> 8; if (flo < 0) flo = 0;
  int fhi = pos >> 8;          if (fhi > NFR-1) fhi = NFR-1;
  const float* fbuf = g_frames + (size_t)b * NFR * 2048;
  float acc = 0.f;
  for (int f = flo; f <= fhi; ++f)
    acc += fbuf[(size_t)f*2048 + (pos - (f<<8))];
  float e = g_env[pos];
  float r = acc / (e > 1e-11f ? e : 1.0f);
  if (is_final) out_final[gid] = r;
  else          g_inv[gid] = r;
}

// ---------------- STFT of inv (2 frames packed) + phase update ----------------
__global__ void k_stft_update(){
  __shared__ float Zr[ZLEN], Zi[ZLEN];
  int tid = threadIdx.x;
  int pb = blockIdx.x;
  int b = pb / NPT, pt = pb % NPT;
  int t0 = 2*pt;
  bool hasB = (t0 + 1 < NFR);
  int fr0 = b*NFR + t0;
  const float* xb = g_inv + (size_t)b * T_LEN;
  for (int k = tid; k < 2048; k += 256){
    float w = g_win[k];
    Zr[PAD(k)] = xb[refl(t0*HOP + k - 1024, T_LEN)] * w;
    float vb = 0.f;
    if (hasB) vb = xb[refl((t0+1)*HOP + k - 1024, T_LEN)] * w;
    Zi[PAD(k)] = vb;
  }
  __syncthreads();
  fft2048_r8<1>(Zr, Zi, tid);
  float2* angp = g_ang   + (size_t)fr0*NBINS;
  float2* tpp  = g_tprev + (size_t)fr0*NBINS;
  for (int k = tid; k <= 1024; k += 256){
    int m = (2048 - k) & 2047;
    float zkr=Zr[PAD(k)], zki=Zi[PAD(k)], zmr=Zr[PAD(m)], zmi=Zi[PAD(m)];
    float rar = 0.5f*(zkr + zmr), rai = 0.5f*(zki - zmi);
    float dr = zkr - zmr, di = zki + zmi;
    float rbr = 0.5f*di, rbi = -0.5f*dr;
    float2 tp = tpp[k];
    float ax = rar - MOM*tp.x, ay = rai - MOM*tp.y;
    float mg = sqrtf(ax*ax + ay*ay) + 1e-16f;
    angp[k] = make_float2(ax/mg, ay/mg);
    tpp[k]  = make_float2(rar, rai);
    if (hasB){
      float2 tpb = tpp[NBINS + k];
      float bx = rbr - MOM*tpb.x, by = rbi - MOM*tpb.y;
      float mb = sqrtf(bx*bx + by*by) + 1e-16f;
      angp[NBINS + k] = make_float2(bx/mb, by/mb);
      tpp[NBINS + k]  = make_float2(rbr, rbi);
    }
  }
}

// ---------------- launch (single stream, serial) ----------------
extern "C" void kernel_launch(void* const* d_in, const int* in_sizes, int n_in,
                              void* d_out, int out_size){
  const float* x  = (const float*)d_in[0];
  const float* W1 = (const float*)d_in[1];
  const float* b1 = (const float*)d_in[2];
  const float* W2 = (const float*)d_in[3];
  const float* b2 = (const float*)d_in[4];
  const float* W3 = (const float*)d_in[5];
  const float* b3 = (const float*)d_in[6];
  float* out  = (float*)d_out;
  float* outc = out + (size_t)BATCH*T_LEN;

  // jax.random.key(42)=(0,42); partitionable split:
  // kr = threefry((0,42),(0,0)), ki = threefry((0,42),(0,1))
  unsigned kr0,kr1,ki0,ki1;
  tf2x32(0u, 42u, 0u, 0u, kr0, kr1);
  tf2x32(0u, 42u, 0u, 1u, ki0, ki1);

  k_fpts<<<1, 128>>>();
  k_tables<<<(2048+L_OLA+NBINS + 255)/256, 256>>>();
  k_angles<<<(NTOT + 255)/256, 256>>>(kr0, kr1, ki0, ki1);
  k_feats_mlp<<<NFRT/8, 256>>>(x, W1, b1, W2, b2, W3, b3, outc);
  k_stft_lin<<<NPAIR, 256>>>(x);
  for (int it = 0; it < 4; ++it){
    k_ifft_frames<<<NPAIR, 256>>>();
    k_ola<<<(BATCH*T_LEN)/256, 256>>>(out, 0);
    k_stft_update<<<NPAIR, 256>>>();
  }
  k_ifft_frames<<<NPAIR, 256>>>();
  k_ola<<<(BATCH*T_LEN)/256, 256>>>(out, 1);
}